// round 5
// baseline (speedup 1.0000x reference)
#include <cuda_runtime.h>
#include <cuda_bf16.h>
#include <cstdint>

#define BB 2
#define HH 16
#define LL 2048
#define DD 64
#define TOPK 64
#define QT 16            // queries per CTA
#define KC 128           // keys per chunk
#define NCHUNK (LL/KC)   // 16
#define NTHREADS 256
#define NWARP 8
#define CAP 224          // candidate capacity per query
#define NLOAD 7          // CAP/32

// ---- smem offsets (bytes) ----
#define KBUF_OFF 0
#define KSTAGE   32768                     // khi 16K + klo 16K
#define QHI_OFF  65536
#define QLO_OFF  67584
#define CAND_OFF 69632                     // 16*224*8 = 28672
#define CNT_OFF  98304
#define THR_OFF  98368
#define SIDX_OFF 98432                     // 16*64*4
#define SVAL_OFF 102528                    // 16*64*4
#define HIST_OFF 106624                    // 8 warps * 256 u16 = 4096
#define SMEM_BYTES 110720                  // x2 CTAs = 221440 < SM limit

// ---- persistent bf16 hi/lo split of K (prep kernel output) ----
#define PREP_N (BB*HH*LL*DD/4)
__device__ __align__(16) uint2 KhiG[PREP_N];   // 8MB
__device__ __align__(16) uint2 KloG[PREP_N];   // 8MB

__device__ __forceinline__ uint32_t swz(uint32_t o) { return o ^ ((o >> 3) & 0x70u); }
__device__ __forceinline__ uint32_t sptr(const void* p) {
    return (uint32_t)__cvta_generic_to_shared(p);
}
__device__ __forceinline__ uint32_t pack_bf16(float a, float b) {
    __nv_bfloat162 t = __floats2bfloat162_rn(a, b);
    return *reinterpret_cast<uint32_t*>(&t);
}
__device__ __forceinline__ void cp_async16(uint32_t dst, const void* src) {
    asm volatile("cp.async.cg.shared.global [%0], [%1], 16;" :: "r"(dst), "l"(src));
}
__device__ __forceinline__ void ldsm_x4(uint32_t a[4], uint32_t addr) {
    asm volatile("ldmatrix.sync.aligned.m8n8.x4.shared.b16 {%0,%1,%2,%3}, [%4];"
                 : "=r"(a[0]), "=r"(a[1]), "=r"(a[2]), "=r"(a[3]) : "r"(addr));
}
__device__ __forceinline__ void ldsm_x2(uint32_t b[2], uint32_t addr) {
    asm volatile("ldmatrix.sync.aligned.m8n8.x2.shared.b16 {%0,%1}, [%2];"
                 : "=r"(b[0]), "=r"(b[1]) : "r"(addr));
}
__device__ __forceinline__ void mma16816(float c[4], const uint32_t a[4], const uint32_t b[2]) {
    asm volatile("mma.sync.aligned.m16n8k16.row.col.f32.bf16.bf16.f32 "
                 "{%0,%1,%2,%3}, {%4,%5,%6,%7}, {%8,%9}, {%0,%1,%2,%3};"
                 : "+f"(c[0]), "+f"(c[1]), "+f"(c[2]), "+f"(c[3])
                 : "r"(a[0]), "r"(a[1]), "r"(a[2]), "r"(a[3]), "r"(b[0]), "r"(b[1]));
}
__device__ __forceinline__ unsigned ordbits(unsigned u) {
    return (u & 0x80000000u) ? ~u : (u | 0x80000000u);
}
__device__ __forceinline__ float invord(unsigned T) {
    unsigned u = (T & 0x80000000u) ? (T & 0x7FFFFFFFu) : ~T;
    return __uint_as_float(u);
}

// ---- prep: split K into bf16 hi + residual-lo ----
__global__ __launch_bounds__(256) void prep_k_kernel(const float4* __restrict__ K) {
    int i = blockIdx.x * 256 + threadIdx.x;
    float4 v = K[i];
    __nv_bfloat162 h01 = __floats2bfloat162_rn(v.x, v.y);
    __nv_bfloat162 h23 = __floats2bfloat162_rn(v.z, v.w);
    float l0 = v.x - __bfloat162float(h01.x);
    float l1 = v.y - __bfloat162float(h01.y);
    float l2 = v.z - __bfloat162float(h23.x);
    float l3 = v.w - __bfloat162float(h23.y);
    KhiG[i] = make_uint2(*reinterpret_cast<uint32_t*>(&h01),
                         *reinterpret_cast<uint32_t*>(&h23));
    KloG[i] = make_uint2(pack_bf16(l0, l1), pack_bf16(l2, l3));
}

// warp-aggregated non-atomic histogram increment (per-warp private bins)
__device__ __forceinline__ void hacc(unsigned short* h, unsigned digit, bool valid, int lane) {
    unsigned kk = valid ? digit : (0x100u + (unsigned)lane);  // invalid -> singleton
    unsigned mm = __match_any_sync(0xFFFFFFFFu, kk);
    if (valid && lane == (__ffs(mm) - 1))
        h[digit] = (unsigned short)(h[digit] + (unsigned)__popc(mm));
    __syncwarp();
}

// suffix scan over 256 u16 bins (high digit = high value): bucket crossing rank r
__device__ __forceinline__ void hscan(const unsigned short* h, int lane, int r,
                                      int& bsel, int& rnew) {
    const unsigned FULL = 0xFFFFFFFFu;
    unsigned hv[8], s = 0;
    int b0 = lane * 8;
#pragma unroll
    for (int j = 0; j < 8; j++) { hv[j] = h[b0 + j]; s += hv[j]; }
    unsigned t = s;
#pragma unroll
    for (int d = 1; d < 32; d <<= 1) {
        unsigned v = __shfl_down_sync(FULL, t, d);
        if (lane + d < 32) t += v;
    }
    unsigned above = t - s;
    bool cross = (above < (unsigned)r) && ((unsigned)r <= t);
    unsigned cmask = __ballot_sync(FULL, cross);
    int src = __ffs(cmask) - 1;
    int bs = 0, rn = 0;
    if (cross) {
        unsigned cum = above;
#pragma unroll
        for (int j = 7; j >= 0; j--) {
            cum += hv[j];
            if (cum >= (unsigned)r) { bs = b0 + j; rn = r - (int)(cum - hv[j]); break; }
        }
    }
    bsel = __shfl_sync(FULL, bs, src);
    rnew = __shfl_sync(FULL, rn, src);
}

// 16-bit-key select over the candidate buffer of query q (2-round histogram).
// final=false: compact to key16 >= T16, update cnt/thr.
// final=true : emit exactly TOPK (val,idx), ties at T16 by ascending idx,
//              rank-sorted by idx for deterministic reduction order.
__device__ __forceinline__ void select16(uint2* cand, unsigned* cnt, float* thr,
                                         int* sidx, float* sval, unsigned short* hw,
                                         int q, int lane, bool final_phase)
{
    const unsigned FULL = 0xFFFFFFFFu;
    uint2* buf = cand + q * CAP;
    const int n = min((int)cnt[q], CAP);
    uint2 e[NLOAD]; unsigned key[NLOAD];
#pragma unroll
    for (int j = 0; j < NLOAD; j++) {
        int s = j * 32 + lane;
        if (s < n) { e[j] = buf[s]; key[j] = ordbits(e[j].x); }
        else       { e[j] = make_uint2(0u, 0u); key[j] = 0u; }
    }
    uint32_t* h32 = (uint32_t*)hw;
    // round A: top byte
    h32[lane] = 0; h32[lane + 32] = 0; h32[lane + 64] = 0; h32[lane + 96] = 0;
    __syncwarp();
#pragma unroll
    for (int j = 0; j < NLOAD; j++)
        hacc(hw, key[j] >> 24, (j * 32 + lane) < n, lane);
    int b1, r1; hscan(hw, lane, TOPK, b1, r1);
    __syncwarp();
    // round B: second byte within bucket b1
    h32[lane] = 0; h32[lane + 32] = 0; h32[lane + 64] = 0; h32[lane + 96] = 0;
    __syncwarp();
#pragma unroll
    for (int j = 0; j < NLOAD; j++)
        hacc(hw, (key[j] >> 16) & 255u,
             ((j * 32 + lane) < n) && ((key[j] >> 24) == (unsigned)b1), lane);
    int b0sel, r2; hscan(hw, lane, r1, b0sel, r2);
    const unsigned T16 = ((unsigned)b1 << 8) | (unsigned)b0sel;
    const unsigned ltm = (1u << lane) - 1u;

    if (!final_phase) {
        int base = 0;
#pragma unroll
        for (int j = 0; j < NLOAD; j++) {
            bool pv = ((j * 32 + lane) < n) && ((key[j] >> 16) >= T16);
            unsigned m = __ballot_sync(FULL, pv);
            if (pv) buf[base + __popc(m & ltm)] = e[j];
            base += __popc(m);
        }
        if (lane == 0) { cnt[q] = (unsigned)base; thr[q] = invord(T16 << 16); }
    } else {
        int* qi = sidx + q * 64;
        float* qv = sval + q * 64;
        int base = 0;
#pragma unroll
        for (int j = 0; j < NLOAD; j++) {
            bool pv = ((j * 32 + lane) < n) && ((key[j] >> 16) > T16);
            unsigned m = __ballot_sync(FULL, pv);
            if (pv) {
                int p = base + __popc(m & ltm);
                qi[p] = (int)e[j].y;
                qv[p] = __uint_as_float(e[j].x);
            }
            base += __popc(m);
        }
        int need = TOPK - base;        // >= 1 by construction
        unsigned used = 0;
        for (int t = 0; t < need; t++) {
            unsigned best = 0xFFFFFFFFu; int bj = -1;
#pragma unroll
            for (int j = 0; j < NLOAD; j++) {
                bool pe = ((j * 32 + lane) < n) && ((key[j] >> 16) == T16)
                          && !((used >> j) & 1u);
                if (pe && e[j].y < best) { best = e[j].y; bj = j; }
            }
            unsigned m = __reduce_min_sync(FULL, best);
            if (best == m && bj >= 0) {
                used |= 1u << bj;
                qi[base + t] = (int)e[bj].y;
                qv[base + t] = __uint_as_float(e[bj].x);
            }
        }
        __syncwarp();
        // rank-sort by index (indices distinct -> perfect permutation)
        int i0 = qi[lane], i1 = qi[lane + 32];
        float v0 = qv[lane], v1 = qv[lane + 32];
        int r0 = 0, r1s = 0;
        for (int t = 0; t < 32; t++) {
            int u0 = __shfl_sync(FULL, i0, t);
            int u1 = __shfl_sync(FULL, i1, t);
            r0  += (u0 < i0) + (u1 < i0);
            r1s += (u0 < i1) + (u1 < i1);
        }
        __syncwarp();
        qi[r0] = i0;  qv[r0] = v0;
        qi[r1s] = i1; qv[r1s] = v1;
        __syncwarp();
    }
}

__global__ __launch_bounds__(NTHREADS, 2)
void topk_attn_kernel(const float* __restrict__ Qg, const float* __restrict__ Vg,
                      float* __restrict__ Og)
{
    extern __shared__ char smem[];
    char*           qhi  = smem + QHI_OFF;
    char*           qlo  = smem + QLO_OFF;
    uint2*          cand = (uint2*)(smem + CAND_OFF);
    unsigned*       cnt  = (unsigned*)(smem + CNT_OFF);
    float*          thr  = (float*)(smem + THR_OFF);
    int*            sidx = (int*)(smem + SIDX_OFF);
    float*          sval = (float*)(smem + SVAL_OFF);
    unsigned short* hist = (unsigned short*)(smem + HIST_OFF);
    const uint32_t smem_u32 = sptr(smem);

    const int bh = blockIdx.x >> 7;
    const int qt = blockIdx.x & 127;
    const int q0 = qt * QT;
    const float* Qb = Qg + (size_t)bh * LL * DD;
    const float* Vb = Vg + (size_t)bh * LL * DD;

    const int tid  = threadIdx.x;
    const int lane = tid & 31;
    const int warp = tid >> 5;
    const unsigned FULL = 0xFFFFFFFFu;
    unsigned short* hw = hist + warp * 256;

    const char* khiG = (const char*)KhiG + ((size_t)bh * LL) * 128;
    const char* kloG = (const char*)KloG + ((size_t)bh * LL) * 128;
    auto issue_chunk = [&](int ch) {
        const uint32_t dbase = smem_u32 + KBUF_OFF + (ch & 1) * KSTAGE;
        const size_t gbase = (size_t)ch * KC * 128;
#pragma unroll
        for (int it = 0; it < 8; it++) {
            int fi = tid + it * NTHREADS;      // 0..2047
            int half = fi >> 10;               // 0=hi, 1=lo
            uint32_t off = (uint32_t)(fi & 1023) * 16;
            const char* src = (half ? kloG : khiG) + gbase + off;
            cp_async16(dbase + half * 16384 + swz(off), src);
        }
        asm volatile("cp.async.commit_group;" ::: "memory");
    };

    issue_chunk(0);

    if (tid < QT) { cnt[tid] = 128u; thr[tid] = __int_as_float(0xFF800000); }

    // ---- load Q tile (fp32 -> bf16 hi/lo, swizzled) ----
    {
        int qrow = tid >> 4;
        int dc = (tid & 15) * 4;
        float4 qv4 = *(const float4*)(Qb + (size_t)(q0 + qrow) * DD + dc);
        __nv_bfloat162 h01 = __floats2bfloat162_rn(qv4.x, qv4.y);
        __nv_bfloat162 h23 = __floats2bfloat162_rn(qv4.z, qv4.w);
        float l0 = qv4.x - __bfloat162float(h01.x);
        float l1 = qv4.y - __bfloat162float(h01.y);
        float l2 = qv4.z - __bfloat162float(h23.x);
        float l3 = qv4.w - __bfloat162float(h23.y);
        uint32_t off = swz((uint32_t)(qrow * 128 + dc * 2));
        *(uint2*)(qhi + off) = make_uint2(*reinterpret_cast<uint32_t*>(&h01),
                                          *reinterpret_cast<uint32_t*>(&h23));
        *(uint2*)(qlo + off) = make_uint2(pack_bf16(l0, l1), pack_bf16(l2, l3));
    }
    __syncthreads();

    // ---- preload B fragments: both n-tiles, 4 k-steps ----
    uint32_t Bh[2][4][2], Bl[2][4][2];
#pragma unroll
    for (int nt2 = 0; nt2 < 2; nt2++) {
        int qrow = nt2 * 8 + (lane & 7);
        int cb = ((lane >> 3) & 1) * 16;
#pragma unroll
        for (int ks = 0; ks < 4; ks++) {
            uint32_t off = swz((uint32_t)(qrow * 128 + ks * 32 + cb));
            ldsm_x2(Bh[nt2][ks], sptr(qhi + off));
            ldsm_x2(Bl[nt2][ks], sptr(qlo + off));
        }
    }
    uint32_t aoff[4];
#pragma unroll
    for (int ks = 0; ks < 4; ks++)
        aoff[ks] = swz((uint32_t)((warp * 16 + (lane & 15)) * 128 +
                                  ks * 32 + ((lane >> 4) & 1) * 16));

    const int qc = 2 * (lane & 3);
    // register-cached thresholds for the 4 queries this thread appends to
    float tr0 = __int_as_float(0xFF800000), tr1 = tr0, tr2 = tr0, tr3 = tr0;

    // ---- main loop ----
    for (int ch = 0; ch < NCHUNK; ch++) {
        asm volatile("cp.async.wait_group 0;" ::: "memory");
        __syncthreads();
        if (ch + 1 < NCHUNK) issue_chunk(ch + 1);

        const uint32_t khi = smem_u32 + KBUF_OFF + (ch & 1) * KSTAGE;
        const uint32_t klo = khi + 16384;

        float a0[4] = {0.f, 0.f, 0.f, 0.f};
        float a1[4] = {0.f, 0.f, 0.f, 0.f};
#pragma unroll
        for (int ks = 0; ks < 4; ks++) {
            uint32_t Ah[4], Al[4];
            ldsm_x4(Ah, khi + aoff[ks]);
            ldsm_x4(Al, klo + aoff[ks]);
            mma16816(a0, Ah, Bh[0][ks]);
            mma16816(a0, Al, Bh[0][ks]);
            mma16816(a0, Ah, Bl[0][ks]);
            mma16816(a1, Ah, Bh[1][ks]);
            mma16816(a1, Al, Bh[1][ks]);
            mma16816(a1, Ah, Bl[1][ks]);
        }

        const int r0 = warp * 16 + (lane >> 2);
        if (ch == 0) {
            cand[(qc    ) * CAP + r0    ] = make_uint2(__float_as_uint(a0[0]), (unsigned)r0);
            cand[(qc + 1) * CAP + r0    ] = make_uint2(__float_as_uint(a0[1]), (unsigned)r0);
            cand[(qc    ) * CAP + r0 + 8] = make_uint2(__float_as_uint(a0[2]), (unsigned)(r0 + 8));
            cand[(qc + 1) * CAP + r0 + 8] = make_uint2(__float_as_uint(a0[3]), (unsigned)(r0 + 8));
            cand[(qc + 8) * CAP + r0    ] = make_uint2(__float_as_uint(a1[0]), (unsigned)r0);
            cand[(qc + 9) * CAP + r0    ] = make_uint2(__float_as_uint(a1[1]), (unsigned)r0);
            cand[(qc + 8) * CAP + r0 + 8] = make_uint2(__float_as_uint(a1[2]), (unsigned)(r0 + 8));
            cand[(qc + 9) * CAP + r0 + 8] = make_uint2(__float_as_uint(a1[3]), (unsigned)(r0 + 8));
        } else {
            const int kr = ch * KC + r0;
#pragma unroll
            for (int u = 0; u < 8; u++) {
                float v = (u < 4) ? a0[u] : a1[u - 4];
                float tv = (u & 1) ? ((u < 4) ? tr1 : tr3) : ((u < 4) ? tr0 : tr2);
                if (v > tv) {
                    int q = qc + ((u < 4) ? 0 : 8) + (u & 1);
                    int k = kr + ((u & 2) ? 8 : 0);
                    unsigned p = atomicAdd(&cnt[q], 1u);
                    if (p < CAP) cand[q * CAP + p] =
                        make_uint2(__float_as_uint(v), (unsigned)k);
                }
            }
        }

        // compaction at seen = 128, 256, 512, 1024 keys
        if (ch == 0 || ch == 1 || ch == 3 || ch == 7) {
            __syncthreads();
            select16(cand, cnt, thr, sidx, sval, hw, warp,     lane, false);
            select16(cand, cnt, thr, sidx, sval, hw, warp + 8, lane, false);
            __syncthreads();
            tr0 = thr[qc];     tr1 = thr[qc + 1];
            tr2 = thr[qc + 8]; tr3 = thr[qc + 9];
        }
    }
    __syncthreads();

    // ---- final: top-64, softmax, V gather (warp handles 2 queries) ----
#pragma unroll 1
    for (int qq = 0; qq < 2; qq++) {
        const int q = warp + qq * 8;
        select16(cand, cnt, thr, sidx, sval, hw, q, lane, true);

        const int* qi = sidx + q * 64;
        const float* qv = sval + q * 64;
        int   k0 = qi[lane],      k1 = qi[lane + 32];
        float v0 = qv[lane],      v1 = qv[lane + 32];
        float m = fmaxf(v0, v1);
#pragma unroll
        for (int o = 16; o; o >>= 1) m = fmaxf(m, __shfl_xor_sync(FULL, m, o));
        float e0 = __expf(v0 - m), e1 = __expf(v1 - m);
        float s = e0 + e1;
#pragma unroll
        for (int o = 16; o; o >>= 1) s += __shfl_xor_sync(FULL, s, o);
        float inv = 1.f / s;
        float w0 = e0 * inv, w1 = e1 * inv;

        float o0 = 0.f, o1 = 0.f;
#pragma unroll 8
        for (int i = 0; i < 32; i++) {
            float wa = __shfl_sync(FULL, w0, i); int ka = __shfl_sync(FULL, k0, i);
            float wb = __shfl_sync(FULL, w1, i); int kb = __shfl_sync(FULL, k1, i);
            const float* ra = Vb + (size_t)ka * DD;
            const float* rb = Vb + (size_t)kb * DD;
            o0 += wa * ra[lane];      o1 += wa * ra[lane + 32];
            o0 += wb * rb[lane];      o1 += wb * rb[lane + 32];
        }
        size_t ob = ((size_t)bh * LL + q0 + q) * DD;
        Og[ob + lane]      = o0;
        Og[ob + lane + 32] = o1;
    }
}

extern "C" void kernel_launch(void* const* d_in, const int* in_sizes, int n_in,
                              void* d_out, int out_size)
{
    (void)in_sizes; (void)n_in; (void)out_size;
    const float* Q = (const float*)d_in[0];
    const float* K = (const float*)d_in[1];
    const float* V = (const float*)d_in[2];
    float* O = (float*)d_out;

    prep_k_kernel<<<PREP_N / 256, 256>>>((const float4*)K);

    cudaFuncSetAttribute(topk_attn_kernel,
                         cudaFuncAttributeMaxDynamicSharedMemorySize, SMEM_BYTES);
    dim3 grid(BB * HH * (LL / QT));   // 4096 CTAs
    topk_attn_kernel<<<grid, NTHREADS, SMEM_BYTES>>>(Q, V, O);
}

// round 6
// speedup vs baseline: 2.1002x; 2.1002x over previous
#include <cuda_runtime.h>
#include <cuda_bf16.h>
#include <cstdint>

#define BB 2
#define HH 16
#define LL 2048
#define DD 64
#define TOPK 64
#define QT 16           // queries per CTA
#define KC 128          // keys per chunk
#define NCHUNK (LL/KC)  // 16
#define NWARP 16
#define NTHREADS 512
#define SCORE_STRIDE 2052   // padded fp32 stride

// ---- smem layout (bytes) ----
#define SC_BYTES   (QT*SCORE_STRIDE*4)        // 131328
#define KBUF_OFF   SC_BYTES
#define KSTAGE     32768                      // khi(16K) + klo(16K) per stage
#define QHI_OFF    (KBUF_OFF + 2*KSTAGE)      // +65536
#define QLO_OFF    (QHI_OFF + QT*128)         // +2048
#define HIST_OFF   (QLO_OFF + QT*128)         // +2048
#define SIDX_OFF   (HIST_OFF + NWARP*256*4)   // +16384
#define EIDX_OFF   (SIDX_OFF + NWARP*64*4)    // +4096
#define SMEM_BYTES (EIDX_OFF + NWARP*64*4)    // 225536 total

// ---- persistent bf16 hi/lo split of K (prep kernel output) ----
#define PREP_N (BB*HH*LL*DD/4)   // 1,048,576 float4 groups
__device__ __align__(16) uint2 KhiG[PREP_N];   // 8MB
__device__ __align__(16) uint2 KloG[PREP_N];   // 8MB

__device__ __forceinline__ uint32_t swz(uint32_t o) { return o ^ ((o >> 3) & 0x70u); }
__device__ __forceinline__ uint32_t sptr(const void* p) {
    return (uint32_t)__cvta_generic_to_shared(p);
}
__device__ __forceinline__ uint32_t pack_bf16(float a, float b) {
    __nv_bfloat162 t = __floats2bfloat162_rn(a, b);
    return *reinterpret_cast<uint32_t*>(&t);
}
__device__ __forceinline__ void cp_async16(uint32_t dst, const void* src) {
    asm volatile("cp.async.cg.shared.global [%0], [%1], 16;" :: "r"(dst), "l"(src));
}
__device__ __forceinline__ void ldsm_x4(uint32_t a[4], uint32_t addr) {
    asm volatile("ldmatrix.sync.aligned.m8n8.x4.shared.b16 {%0,%1,%2,%3}, [%4];"
                 : "=r"(a[0]), "=r"(a[1]), "=r"(a[2]), "=r"(a[3]) : "r"(addr));
}
__device__ __forceinline__ void mma16816(float c[4], const uint32_t a[4], const uint32_t b[2]) {
    asm volatile("mma.sync.aligned.m16n8k16.row.col.f32.bf16.bf16.f32 "
                 "{%0,%1,%2,%3}, {%4,%5,%6,%7}, {%8,%9}, {%0,%1,%2,%3};"
                 : "+f"(c[0]), "+f"(c[1]), "+f"(c[2]), "+f"(c[3])
                 : "r"(a[0]), "r"(a[1]), "r"(a[2]), "r"(a[3]), "r"(b[0]), "r"(b[1]));
}
// sign-flip trick: monotonic unsigned ordering of floats
__device__ __forceinline__ unsigned ordkey(float f) {
    unsigned u = __float_as_uint(f);
    return (u & 0x80000000u) ? ~u : (u | 0x80000000u);
}

// ---- prep: split K into bf16 hi + residual-lo, stored bf16-row-major ----
__global__ __launch_bounds__(256) void prep_k_kernel(const float4* __restrict__ K) {
    int i = blockIdx.x * 256 + threadIdx.x;
    float4 v = K[i];
    __nv_bfloat162 h01 = __floats2bfloat162_rn(v.x, v.y);
    __nv_bfloat162 h23 = __floats2bfloat162_rn(v.z, v.w);
    float l0 = v.x - __bfloat162float(h01.x);
    float l1 = v.y - __bfloat162float(h01.y);
    float l2 = v.z - __bfloat162float(h23.x);
    float l3 = v.w - __bfloat162float(h23.y);
    KhiG[i] = make_uint2(*reinterpret_cast<uint32_t*>(&h01),
                         *reinterpret_cast<uint32_t*>(&h23));
    KloG[i] = make_uint2(pack_bf16(l0, l1), pack_bf16(l2, l3));
}

// warp-level scan over a 256-bin histogram: find digit bucket crossing rank r
__device__ __forceinline__ void hist_scan(const uint32_t* myhist, int lane, int r,
                                          int& bsel, int& rnew) {
    const unsigned FULL = 0xFFFFFFFFu;
    unsigned h[8], s = 0;
    int b0 = lane * 8;
#pragma unroll
    for (int j = 0; j < 8; j++) { h[j] = myhist[b0 + j]; s += h[j]; }
    unsigned t = s;                 // suffix-inclusive scan (high lanes = high digits)
#pragma unroll
    for (int d = 1; d < 32; d <<= 1) {
        unsigned v = __shfl_down_sync(FULL, t, d);
        if (lane + d < 32) t += v;
    }
    unsigned above = t - s;
    bool cross = (above < (unsigned)r) && ((unsigned)r <= t);
    unsigned cmask = __ballot_sync(FULL, cross);
    int src = __ffs(cmask) - 1;
    int bs = 0, rn = 0;
    if (cross) {
        unsigned cum = above;
#pragma unroll
        for (int j = 7; j >= 0; j--) {
            cum += h[j];
            if (cum >= (unsigned)r) { bs = b0 + j; rn = r - (int)(cum - h[j]); break; }
        }
    }
    bsel = __shfl_sync(FULL, bs, src);
    rnew = __shfl_sync(FULL, rn, src);
}

__global__ __launch_bounds__(NTHREADS, 1)
void topk_attn_kernel(const float* __restrict__ Qg, const float* __restrict__ Vg,
                      float* __restrict__ Og)
{
    extern __shared__ char smem[];
    float*    sc    = (float*)smem;
    char*     qhi   = smem + QHI_OFF;
    char*     qlo   = smem + QLO_OFF;
    uint32_t* hist  = (uint32_t*)(smem + HIST_OFF);
    uint32_t* sidxA = (uint32_t*)(smem + SIDX_OFF);
    uint32_t* eidxA = (uint32_t*)(smem + EIDX_OFF);
    const uint32_t smem_u32 = sptr(smem);

    const int bh = blockIdx.x >> 7;
    const int qt = blockIdx.x & 127;
    const int q0 = qt * QT;
    const float* Qb = Qg + (size_t)bh * LL * DD;
    const float* Vb = Vg + (size_t)bh * LL * DD;

    const int tid  = threadIdx.x;
    const int lane = tid & 31;
    const int warp = tid >> 5;
    const unsigned FULL = 0xFFFFFFFFu;

    // ---- issue K chunk load (bf16 hi/lo, pre-split) via cp.async ----
    const char* khiG = (const char*)KhiG + ((size_t)bh * LL) * 128;
    const char* kloG = (const char*)KloG + ((size_t)bh * LL) * 128;
    auto issue_chunk = [&](int ch) {
        const uint32_t dbase = smem_u32 + KBUF_OFF + (ch & 1) * KSTAGE;
        const size_t gbase = (size_t)ch * KC * 128;
#pragma unroll
        for (int it = 0; it < 4; it++) {
            int fi = tid + it * NTHREADS;       // 0..2047
            int half = fi >> 10;                // 0=hi, 1=lo
            uint32_t off = (uint32_t)(fi & 1023) * 16;
            const char* src = (half ? kloG : khiG) + gbase + off;
            uint32_t dst = dbase + half * 16384 + swz(off);
            cp_async16(dst, src);
        }
        asm volatile("cp.async.commit_group;" ::: "memory");
    };

    issue_chunk(0);   // start DMA before anything else

    // ---- load Q tile, split bf16 hi/lo into swizzled smem ----
    {
        int qrow = tid >> 5;
        int dc = (tid & 31) * 2;
        float2 qv = *(const float2*)(Qb + (size_t)(q0 + qrow) * DD + dc);
        __nv_bfloat162 hp = __floats2bfloat162_rn(qv.x, qv.y);
        float lx = qv.x - __bfloat162float(hp.x);
        float ly = qv.y - __bfloat162float(hp.y);
        uint32_t off = swz((uint32_t)(qrow * 128 + dc * 2));
        *(uint32_t*)(qhi + off) = *reinterpret_cast<uint32_t*>(&hp);
        *(uint32_t*)(qlo + off) = pack_bf16(lx, ly);
    }
    __syncthreads();

    // ---- preload A fragments (Q, m16k16 per k-step) into registers ----
    uint32_t Ah[4][4], Al[4][4];
    {
        int arow = lane & 15;                  // query row
        int acb = ((lane >> 4) & 1) * 16;      // k-halves
#pragma unroll
        for (int ks = 0; ks < 4; ks++) {
            uint32_t off = swz((uint32_t)(arow * 128 + ks * 32 + acb));
            ldsm_x4(Ah[ks], sptr(qhi + off));
            ldsm_x4(Al[ks], sptr(qlo + off));
        }
    }

    // B (K) addressing: warp owns keys [warp*8, warp*8+8) of each chunk.
    // ldsm_x4 covers 2 k-steps: lanes 0-7 ks.k0-7, 8-15 ks.k8-15,
    // 16-23 (ks+1).k0-7, 24-31 (ks+1).k8-15.
    const uint32_t brow_off = (uint32_t)((warp * 8 + (lane & 7)) * 128 +
                                         ((lane >> 3) & 3) * 16);

    // ---- main loop: pipelined K chunks -> 3-pass bf16 MMA -> fp32 scores ----
    for (int ch = 0; ch < NCHUNK; ch++) {
        asm volatile("cp.async.wait_group 0;" ::: "memory");
        __syncthreads();
        if (ch + 1 < NCHUNK) issue_chunk(ch + 1);   // overlap next load with MMA

        const uint32_t khi = smem_u32 + KBUF_OFF + (ch & 1) * KSTAGE;
        const uint32_t klo = khi + 16384;
        const uint32_t b0 = swz(brow_off);          // k-steps 0,1
        const uint32_t b1 = swz(brow_off + 64);     // k-steps 2,3

        uint32_t Bh0[4], Bh1[4], Bl0[4], Bl1[4];
        ldsm_x4(Bh0, khi + b0);
        ldsm_x4(Bh1, khi + b1);
        ldsm_x4(Bl0, klo + b0);
        ldsm_x4(Bl1, klo + b1);

        float acc[4] = {0.f, 0.f, 0.f, 0.f};
        // k-steps 0,1 from Bx0; 2,3 from Bx1
        mma16816(acc, Ah[0], Bh0);      mma16816(acc, Al[0], Bh0);
        mma16816(acc, Ah[0], Bl0);
        mma16816(acc, Ah[1], Bh0 + 2);  mma16816(acc, Al[1], Bh0 + 2);
        mma16816(acc, Ah[1], Bl0 + 2);
        mma16816(acc, Ah[2], Bh1);      mma16816(acc, Al[2], Bh1);
        mma16816(acc, Ah[2], Bl1);
        mma16816(acc, Ah[3], Bh1 + 2);  mma16816(acc, Al[3], Bh1 + 2);
        mma16816(acc, Ah[3], Bl1 + 2);

        // store 16q x 8k accumulator tile (rows = queries, cols = keys)
        {
            int qrow = lane >> 2;
            int kcol = ch * KC + warp * 8 + 2 * (lane & 3);
            *(float2*)&sc[qrow * SCORE_STRIDE + kcol]       = make_float2(acc[0], acc[1]);
            *(float2*)&sc[(qrow + 8) * SCORE_STRIDE + kcol] = make_float2(acc[2], acc[3]);
        }
    }
    __syncthreads();

    // ---- per-warp top-64 select on 16-bit ordered keys (one warp = one query) ----
    const float* row = sc + warp * SCORE_STRIDE;
    uint32_t* myhist = hist + warp * 256;
    uint32_t* sidx = sidxA + warp * 64;
    uint32_t* eidx = eidxA + warp * 64;

    for (int b = lane; b < 256; b += 32) myhist[b] = 0;
    __syncwarp();

    // pack keys into registers + fused round-1 histogram (digit = key>>8)
    uint32_t kp[32];
#pragma unroll
    for (int j = 0; j < 64; j += 2) {
        unsigned u0 = ordkey(row[j * 32 + lane]);
        unsigned u1 = ordkey(row[(j + 1) * 32 + lane]);
        kp[j >> 1] = (u0 >> 16) | (u1 & 0xFFFF0000u);
        atomicAdd(&myhist[u0 >> 24], 1u);
        atomicAdd(&myhist[u1 >> 24], 1u);
    }
    __syncwarp();

    int b1d, r1;
    hist_scan(myhist, lane, TOPK, b1d, r1);
    __syncwarp();

    for (int b = lane; b < 256; b += 32) myhist[b] = 0;
    __syncwarp();
#pragma unroll
    for (int j = 0; j < 64; j++) {
        unsigned k = (j & 1) ? (kp[j >> 1] >> 16) : (kp[j >> 1] & 0xFFFFu);
        if ((int)(k >> 8) == b1d) atomicAdd(&myhist[k & 255u], 1u);
    }
    __syncwarp();

    int b0sel, r2;
    hist_scan(myhist, lane, r1, b0sel, r2);
    const unsigned T16 = ((unsigned)b1d << 8) | (unsigned)b0sel;

    // collect: all keys > T16, then first r2 keys == T16 in index order
    {
        int cnt = 0, ecnt = 0;
        unsigned lt = (1u << lane) - 1u;
#pragma unroll
        for (int j = 0; j < 64; j++) {
            unsigned k = (j & 1) ? (kp[j >> 1] >> 16) : (kp[j >> 1] & 0xFFFFu);
            int i = j * 32 + lane;
            bool gt = (k > T16), eq = (k == T16);
            unsigned mg = __ballot_sync(FULL, gt);
            unsigned me = __ballot_sync(FULL, eq);
            if (gt) sidx[cnt + __popc(mg & lt)] = (uint32_t)i;
            if (eq) {
                int p = ecnt + __popc(me & lt);
                if (p < TOPK) eidx[p] = (uint32_t)i;
            }
            cnt += __popc(mg); ecnt += __popc(me);
        }
        __syncwarp();
        for (int j = lane; j < r2; j += 32) sidx[cnt + j] = eidx[j];
        __syncwarp();
    }

    // ---- softmax over selected (exact fp32) + V gather epilogue ----
    {
        int k0 = (int)sidx[lane], k1 = (int)sidx[lane + 32];
        float v0 = row[k0], v1 = row[k1];
        float m = fmaxf(v0, v1);
#pragma unroll
        for (int o = 16; o; o >>= 1) m = fmaxf(m, __shfl_xor_sync(FULL, m, o));
        float e0 = __expf(v0 - m), e1 = __expf(v1 - m);
        float s = e0 + e1;
#pragma unroll
        for (int o = 16; o; o >>= 1) s += __shfl_xor_sync(FULL, s, o);
        float inv = 1.f / s;
        float w0 = e0 * inv, w1 = e1 * inv;

        float a0 = 0.f, a1 = 0.f;
#pragma unroll 8
        for (int i = 0; i < 32; i++) {
            float wa = __shfl_sync(FULL, w0, i); int ka = __shfl_sync(FULL, k0, i);
            float wb = __shfl_sync(FULL, w1, i); int kb2 = __shfl_sync(FULL, k1, i);
            const float* ra = Vb + (size_t)ka * DD;
            const float* rb = Vb + (size_t)kb2 * DD;
            a0 += wa * ra[lane];      a1 += wa * ra[lane + 32];
            a0 += wb * rb[lane];      a1 += wb * rb[lane + 32];
        }
        size_t ob = ((size_t)bh * LL + q0 + warp) * DD;
        Og[ob + lane] = a0;
        Og[ob + lane + 32] = a1;
    }
}

extern "C" void kernel_launch(void* const* d_in, const int* in_sizes, int n_in,
                              void* d_out, int out_size)
{
    (void)in_sizes; (void)n_in; (void)out_size;
    const float* Q = (const float*)d_in[0];
    const float* K = (const float*)d_in[1];
    const float* V = (const float*)d_in[2];
    float* O = (float*)d_out;

    prep_k_kernel<<<PREP_N / 256, 256>>>((const float4*)K);

    cudaFuncSetAttribute(topk_attn_kernel,
                         cudaFuncAttributeMaxDynamicSharedMemorySize, SMEM_BYTES);
    dim3 grid(BB * HH * (LL / QT));   // 4096 CTAs
    topk_attn_kernel<<<grid, NTHREADS, SMEM_BYTES>>>(Q, V, O);
}